// round 17
// baseline (speedup 1.0000x reference)
#include <cuda_runtime.h>
#include <cuda_fp16.h>

#define CN0 50000
#define CN1 150000
#define CN2 20000
#define CN3 5000
#define CN4 1000
#define CE0 800000
#define CE1 1500000
#define CNNZ 300000
#define DD 64

// ---------------- scratch (static device globals; no allocation) ----------------
__device__ __half g_m0[CN0 * DD];   // fp16 messages (halved gather traffic)
__device__ __half g_m1[CN1 * DD];
__device__ __half g_ms[CN1 * DD];
__device__ __half g_mt[CN0 * DD];
__device__ float g_accA0[CN0 * DD];
__device__ float g_accB0[CN0 * DD];
__device__ float g_accA1[CN1 * DD];
__device__ float g_accB1[CN1 * DD];
// CSR scratch
__device__ int  g_deg0[CN0], g_off0[CN0], g_cur0[CN0];
__device__ int  g_deg1[CN1], g_off1[CN1], g_cur1[CN1];
__device__ int2 g_csr0[CE0];   // {src, coeff_bits} sorted by dst
__device__ int2 g_csr1[CE1];
__device__ int  g_bsum0[256];
__device__ int  g_bsum1[256];

// ---------------- packed f32x2 helpers (Blackwell FFMA2) ----------------
__device__ __forceinline__ unsigned long long pack2(float x, float y) {
    unsigned long long r;
    asm("mov.b64 %0, {%1,%2};" : "=l"(r) : "f"(x), "f"(y));
    return r;
}
__device__ __forceinline__ void fma2(unsigned long long& d, unsigned long long a,
                                     unsigned long long b) {
    asm("fma.rn.f32x2 %0, %1, %2, %0;" : "+l"(d) : "l"(a), "l"(b));
}
__device__ __forceinline__ float2 unpack2(unsigned long long v) {
    float2 f;
    asm("mov.b64 {%0,%1}, %2;" : "=f"(f.x), "=f"(f.y) : "l"(v));
    return f;
}

// fp16 row gather (16 lanes/row, 8B each) — used by scatter_inc2
__device__ __forceinline__ float4 gather_h4(const __half* __restrict__ m,
                                            long row, int sub) {
    uint2 u = reinterpret_cast<const uint2*>(m + row * 64)[sub];
    __half2 h0 = *reinterpret_cast<__half2*>(&u.x);
    __half2 h1 = *reinterpret_cast<__half2*>(&u.y);
    float2 f0 = __half22float2(h0);
    float2 f1 = __half22float2(h1);
    return make_float4(f0.x, f0.y, f1.x, f1.y);
}

// fp16 row gather (8 lanes/row, 16B each) — used by csr_accum
__device__ __forceinline__ void gather_h8(const __half* __restrict__ m,
                                          long row, int sub, float* f) {
    uint4 u = reinterpret_cast<const uint4*>(m + row * 64)[sub];
    float2 f0 = __half22float2(*reinterpret_cast<__half2*>(&u.x));
    float2 f1 = __half22float2(*reinterpret_cast<__half2*>(&u.y));
    float2 f2 = __half22float2(*reinterpret_cast<__half2*>(&u.z));
    float2 f3 = __half22float2(*reinterpret_cast<__half2*>(&u.w));
    f[0] = f0.x; f[1] = f0.y; f[2] = f1.x; f[3] = f1.y;
    f[4] = f2.x; f[5] = f2.y; f[6] = f3.x; f[7] = f3.y;
}

// =====================================================================
// Dual GEMM: out1 = X@W1, out2 = X@W2 (fp16 outputs).  128 rows/block.
// =====================================================================
__global__ __launch_bounds__(256) void gemm64_dual(const float* __restrict__ X,
                                                   const float* __restrict__ W1,
                                                   const float* __restrict__ W2,
                                                   __half* __restrict__ out1,
                                                   __half* __restrict__ out2, int N) {
    __shared__ __align__(16) float sW1[64 * 64];
    __shared__ __align__(16) float sW2[64 * 64];
    __shared__ __align__(16) float sXT[128 * 64];
    int tid = threadIdx.x;
#pragma unroll
    for (int i = 0; i < 16; i++) {
        sW1[tid + i * 256] = W1[tid + i * 256];
        sW2[tid + i * 256] = W2[tid + i * 256];
    }
    long r0 = (long)blockIdx.x * 128;
#pragma unroll
    for (int i = 0; i < 32; i++) {
        int li = tid + i * 256;
        int row = li >> 6, col = li & 63;
        long gr = r0 + row;
        float v = (gr < N) ? X[gr * 64 + col] : 0.f;
        sXT[col * 128 + (((row >> 2) ^ (col & 31)) << 2) + (row & 3)] = v;
    }
    __syncthreads();

    int tx = tid & 15, ty = tid >> 4;
    unsigned long long a1[8][2], a2[8][2];
#pragma unroll
    for (int r = 0; r < 8; r++) { a1[r][0] = a1[r][1] = a2[r][0] = a2[r][1] = 0ull; }

    const float4* sXT4 = (const float4*)sXT;
    const ulonglong2* sW1v = (const ulonglong2*)sW1;
    const ulonglong2* sW2v = (const ulonglong2*)sW2;
    int g0 = 2 * ty, g1 = 2 * ty + 1;
#pragma unroll 8
    for (int k = 0; k < 64; k++) {
        float4 xa = sXT4[k * 32 + (g0 ^ (k & 31))];
        float4 xb = sXT4[k * 32 + (g1 ^ (k & 31))];
        ulonglong2 w1 = sW1v[k * 16 + tx];
        ulonglong2 w2 = sW2v[k * 16 + tx];
        float xs[8] = {xa.x, xa.y, xa.z, xa.w, xb.x, xb.y, xb.z, xb.w};
#pragma unroll
        for (int r = 0; r < 8; r++) {
            unsigned long long xx = pack2(xs[r], xs[r]);
            fma2(a1[r][0], xx, w1.x); fma2(a1[r][1], xx, w1.y);
            fma2(a2[r][0], xx, w2.x); fma2(a2[r][1], xx, w2.y);
        }
    }
#pragma unroll
    for (int r = 0; r < 8; r++) {
        long row = r0 + ty * 8 + r;
        if (row < N) {
            float2 lo = unpack2(a1[r][0]), hi = unpack2(a1[r][1]);
            __half2 h0 = __floats2half2_rn(lo.x, lo.y);
            __half2 h1 = __floats2half2_rn(hi.x, hi.y);
            uint2 o;
            o.x = *reinterpret_cast<unsigned int*>(&h0);
            o.y = *reinterpret_cast<unsigned int*>(&h1);
            reinterpret_cast<uint2*>(out1)[row * 16 + tx] = o;
            lo = unpack2(a2[r][0]); hi = unpack2(a2[r][1]);
            h0 = __floats2half2_rn(lo.x, lo.y);
            h1 = __floats2half2_rn(hi.x, hi.y);
            o.x = *reinterpret_cast<unsigned int*>(&h0);
            o.y = *reinterpret_cast<unsigned int*>(&h1);
            reinterpret_cast<uint2*>(out2)[row * 16 + tx] = o;
        }
    }
}

// =====================================================================
// Fused epilogue: out = relu((relu(A)+relu(B)) @ W)   (fp32 in/out)
// =====================================================================
__global__ __launch_bounds__(256) void gemm64_fused(const float* __restrict__ A,
                                                    const float* __restrict__ B,
                                                    const float* __restrict__ W,
                                                    float* __restrict__ out, int N) {
    __shared__ __align__(16) float sW[64 * 64];
    __shared__ __align__(16) float sXT[128 * 64];
    int tid = threadIdx.x;
#pragma unroll
    for (int i = 0; i < 16; i++) sW[tid + i * 256] = W[tid + i * 256];
    long r0 = (long)blockIdx.x * 128;
#pragma unroll
    for (int i = 0; i < 32; i++) {
        int li = tid + i * 256;
        int row = li >> 6, col = li & 63;
        long gr = r0 + row;
        float v = 0.f;
        if (gr < N) {
            long idx = gr * 64 + col;
            v = fmaxf(A[idx], 0.f) + fmaxf(B[idx], 0.f);
        }
        sXT[col * 128 + (((row >> 2) ^ (col & 31)) << 2) + (row & 3)] = v;
    }
    __syncthreads();

    int tx = tid & 15, ty = tid >> 4;
    unsigned long long a1[8][2];
#pragma unroll
    for (int r = 0; r < 8; r++) { a1[r][0] = a1[r][1] = 0ull; }

    const float4* sXT4 = (const float4*)sXT;
    const ulonglong2* sWv = (const ulonglong2*)sW;
    int g0 = 2 * ty, g1 = 2 * ty + 1;
#pragma unroll 8
    for (int k = 0; k < 64; k++) {
        float4 xa = sXT4[k * 32 + (g0 ^ (k & 31))];
        float4 xb = sXT4[k * 32 + (g1 ^ (k & 31))];
        ulonglong2 w = sWv[k * 16 + tx];
        float xs[8] = {xa.x, xa.y, xa.z, xa.w, xb.x, xb.y, xb.z, xb.w};
#pragma unroll
        for (int r = 0; r < 8; r++) {
            unsigned long long xx = pack2(xs[r], xs[r]);
            fma2(a1[r][0], xx, w.x); fma2(a1[r][1], xx, w.y);
        }
    }
#pragma unroll
    for (int r = 0; r < 8; r++) {
        long row = r0 + ty * 8 + r;
        if (row < N) {
            float2 lo = unpack2(a1[r][0]), hi = unpack2(a1[r][1]);
            ((float4*)out)[row * 16 + tx] =
                make_float4(fmaxf(lo.x, 0.f), fmaxf(lo.y, 0.f),
                            fmaxf(hi.x, 0.f), fmaxf(hi.y, 0.f));
        }
    }
}

// ======================= CSR build kernels =======================
__global__ __launch_bounds__(256) void hist_kernel(const int* __restrict__ dst,
                                                   int* __restrict__ deg, int E) {
    int e = blockIdx.x * blockDim.x + threadIdx.x;
    if (e < E) atomicAdd(&deg[dst[e]], 1);
}

__global__ __launch_bounds__(1024) void scan_block(const int* __restrict__ in,
                                                   int* __restrict__ out,
                                                   int* __restrict__ bsum, int N) {
    __shared__ int s[1024];
    int gid = blockIdx.x * 1024 + threadIdx.x;
    int v = (gid < N) ? in[gid] : 0;
    s[threadIdx.x] = v;
    __syncthreads();
#pragma unroll
    for (int d = 1; d < 1024; d <<= 1) {
        int t = (threadIdx.x >= d) ? s[threadIdx.x - d] : 0;
        __syncthreads();
        s[threadIdx.x] += t;
        __syncthreads();
    }
    if (gid < N) out[gid] = s[threadIdx.x] - v;  // exclusive
    if (threadIdx.x == 1023) bsum[blockIdx.x] = s[1023];
}

__global__ __launch_bounds__(256) void scan_top(int* __restrict__ bsum, int nb) {
    __shared__ int s[256];
    int v = (threadIdx.x < nb) ? bsum[threadIdx.x] : 0;
    s[threadIdx.x] = v;
    __syncthreads();
#pragma unroll
    for (int d = 1; d < 256; d <<= 1) {
        int t = (threadIdx.x >= d) ? s[threadIdx.x - d] : 0;
        __syncthreads();
        s[threadIdx.x] += t;
        __syncthreads();
    }
    if (threadIdx.x < nb) bsum[threadIdx.x] = s[threadIdx.x] - v;
}

__global__ __launch_bounds__(256) void scan_add(int* __restrict__ off,
                                                const int* __restrict__ bsum,
                                                int* __restrict__ cur, int N) {
    int gid = blockIdx.x * blockDim.x + threadIdx.x;
    if (gid < N) {
        int o = off[gid] + bsum[gid >> 10];
        off[gid] = o;
        cur[gid] = o;
    }
}

__global__ __launch_bounds__(256) void reorder_adj(const int* __restrict__ src,
                                                   const int* __restrict__ dst,
                                                   const float* __restrict__ val,
                                                   const float* __restrict__ cci,
                                                   const float* __restrict__ a,
                                                   int* __restrict__ cur,
                                                   int2* __restrict__ csr, int E) {
    int e = blockIdx.x * blockDim.x + threadIdx.x;
    if (e >= E) return;
    float c = val[e] * (cci[e * 3 + 0] * a[0] + cci[e * 3 + 1] * a[1] +
                        cci[e * 3 + 2] * a[2]);
    int pos = atomicAdd(&cur[dst[e]], 1);
    csr[pos] = make_int2(src[e], __float_as_int(c));
}

// =====================================================================
// CSR gather-side segment sum: 8 lanes/node, 16B fp16 loads (one LDG.128
// per 8-lane group covers a full 128B message row -> 4 edge-rows per
// warp instruction), fp32 register accumulate, unroll-4 edge loop,
// 2x STG.128 per lane at the end.
// =====================================================================
__global__ __launch_bounds__(256) void csr_accum(const int* __restrict__ off,
                                                 const int* __restrict__ deg,
                                                 const int2* __restrict__ csr,
                                                 const __half* __restrict__ m,
                                                 float* __restrict__ acc, int N) {
    int tid = threadIdx.x;
    int node = blockIdx.x * 32 + (tid >> 3);
    if (node >= N) return;
    int sub = tid & 7;
    int start = off[node];
    int d = deg[node];
    float s[8];
#pragma unroll
    for (int i = 0; i < 8; i++) s[i] = 0.f;
    float v0[8], v1[8], v2[8], v3[8];
    int j = 0;
    for (; j + 4 <= d; j += 4) {
        int2 e0 = csr[start + j];
        int2 e1 = csr[start + j + 1];
        int2 e2 = csr[start + j + 2];
        int2 e3 = csr[start + j + 3];
        gather_h8(m, e0.x, sub, v0);
        gather_h8(m, e1.x, sub, v1);
        gather_h8(m, e2.x, sub, v2);
        gather_h8(m, e3.x, sub, v3);
        float c0 = __int_as_float(e0.y), c1 = __int_as_float(e1.y);
        float c2 = __int_as_float(e2.y), c3 = __int_as_float(e3.y);
#pragma unroll
        for (int i = 0; i < 8; i++) {
            s[i] = fmaf(c0, v0[i], s[i]);
            s[i] = fmaf(c1, v1[i], s[i]);
            s[i] = fmaf(c2, v2[i], s[i]);
            s[i] = fmaf(c3, v3[i], s[i]);
        }
    }
    for (; j < d; j++) {
        int2 e0 = csr[start + j];
        gather_h8(m, e0.x, sub, v0);
        float c0 = __int_as_float(e0.y);
#pragma unroll
        for (int i = 0; i < 8; i++) s[i] = fmaf(c0, v0[i], s[i]);
    }
    float4* o = reinterpret_cast<float4*>(acc + (long)node * 64 + sub * 8);
    o[0] = make_float4(s[0], s[1], s[2], s[3]);
    o[1] = make_float4(s[4], s[5], s[6], s[7]);
}

// =====================================================================
// Incidence scatter (fp16 gathers, fp32 RED, ILP-2 x 2 directions).
// =====================================================================
__global__ __launch_bounds__(256) void scatter_inc2(const __half* __restrict__ ms,
                                                    const __half* __restrict__ mt,
                                                    const int* __restrict__ row,
                                                    const int* __restrict__ col,
                                                    const float* __restrict__ val,
                                                    float* __restrict__ accB0,
                                                    float* __restrict__ accB1, int E) {
    int base = blockIdx.x * 32;
    int tid = threadIdx.x;
    int le = tid >> 4, sub = tid & 15;
    int e0 = base + le;
    int e1 = base + 16 + le;

    int r0 = row[e0], r1 = row[e1];
    int c0 = col[e0], c1 = col[e1];
    float v0 = val[e0], v1 = val[e1];

    float4 a0 = gather_h4(ms, c0, sub);
    float4 a1 = gather_h4(ms, c1, sub);
    float4 b0 = gather_h4(mt, r0, sub);
    float4 b1 = gather_h4(mt, r1, sub);

    a0.x *= v0; a0.y *= v0; a0.z *= v0; a0.w *= v0;
    a1.x *= v1; a1.y *= v1; a1.z *= v1; a1.w *= v1;
    b0.x *= v0; b0.y *= v0; b0.z *= v0; b0.w *= v0;
    b1.x *= v1; b1.y *= v1; b1.z *= v1; b1.w *= v1;

    float* pa0 = accB0 + (long)r0 * 64 + sub * 4;
    float* pa1 = accB0 + (long)r1 * 64 + sub * 4;
    float* pb0 = accB1 + (long)c0 * 64 + sub * 4;
    float* pb1 = accB1 + (long)c1 * 64 + sub * 4;
    asm volatile("red.global.add.v4.f32 [%0], {%1,%2,%3,%4};"
                 :: "l"(pa0), "f"(a0.x), "f"(a0.y), "f"(a0.z), "f"(a0.w) : "memory");
    asm volatile("red.global.add.v4.f32 [%0], {%1,%2,%3,%4};"
                 :: "l"(pa1), "f"(a1.x), "f"(a1.y), "f"(a1.z), "f"(a1.w) : "memory");
    asm volatile("red.global.add.v4.f32 [%0], {%1,%2,%3,%4};"
                 :: "l"(pb0), "f"(b0.x), "f"(b0.y), "f"(b0.z), "f"(b0.w) : "memory");
    asm volatile("red.global.add.v4.f32 [%0], {%1,%2,%3,%4};"
                 :: "l"(pb1), "f"(b1.x), "f"(b1.y), "f"(b1.z), "f"(b1.w) : "memory");
}

// ---------------- stream/event pool: LAZY init, 3 streams ----------------
static cudaStream_t s1 = 0, s2 = 0, s3 = 0;
static cudaEvent_t eRoot = 0, eB1 = 0, eG0 = 0, eG1 = 0, eI = 0, eF0 = 0;
static int g_init_state = 0;

static void ensure_init() {
    if (g_init_state != 0) return;
    bool ok = true;
    ok &= (cudaStreamCreateWithFlags(&s1, cudaStreamNonBlocking) == cudaSuccess);
    ok &= (cudaStreamCreateWithFlags(&s2, cudaStreamNonBlocking) == cudaSuccess);
    ok &= (cudaStreamCreateWithFlags(&s3, cudaStreamNonBlocking) == cudaSuccess);
    ok &= (cudaEventCreateWithFlags(&eRoot, cudaEventDisableTiming) == cudaSuccess);
    ok &= (cudaEventCreateWithFlags(&eB1, cudaEventDisableTiming) == cudaSuccess);
    ok &= (cudaEventCreateWithFlags(&eG0, cudaEventDisableTiming) == cudaSuccess);
    ok &= (cudaEventCreateWithFlags(&eG1, cudaEventDisableTiming) == cudaSuccess);
    ok &= (cudaEventCreateWithFlags(&eI, cudaEventDisableTiming) == cudaSuccess);
    ok &= (cudaEventCreateWithFlags(&eF0, cudaEventDisableTiming) == cudaSuccess);
    g_init_state = ok ? 1 : -1;
}

// ---------------- launch ----------------
extern "C" void kernel_launch(void* const* d_in, const int* in_sizes, int n_in,
                              void* d_out, int out_size) {
    ensure_init();

    const float* x0   = (const float*)d_in[0];
    const float* x1   = (const float*)d_in[1];
    const float* x2   = (const float*)d_in[2];
    const float* x3   = (const float*)d_in[3];
    const float* x4   = (const float*)d_in[4];
    const int*   adj0 = (const int*)d_in[5];
    const float* adj0v= (const float*)d_in[6];
    const int*   adj1 = (const int*)d_in[7];
    const float* adj1v= (const float*)d_in[8];
    const int*   inc  = (const int*)d_in[9];
    const float* incv = (const float*)d_in[10];
    const float* cci0 = (const float*)d_in[11];
    const float* cci1 = (const float*)d_in[12];
    const float* Whbs0= (const float*)d_in[13];
    const float* ahbs0= (const float*)d_in[14];
    const float* Whbs1= (const float*)d_in[15];
    const float* ahbs1= (const float*)d_in[16];
    const float* Ws   = (const float*)d_in[17];
    const float* Wt   = (const float*)d_in[18];
    const float* Wag0 = (const float*)d_in[19];
    const float* Wag1 = (const float*)d_in[20];
    float* out = (float*)d_out;

    __half *pm0, *pm1, *pms, *pmt;
    float *pA0, *pB0, *pA1, *pB1;
    int *pdeg0, *poff0, *pcur0, *pdeg1, *poff1, *pcur1, *pbs0, *pbs1;
    int2 *pcsr0, *pcsr1;
    cudaGetSymbolAddress((void**)&pm0, g_m0);
    cudaGetSymbolAddress((void**)&pm1, g_m1);
    cudaGetSymbolAddress((void**)&pms, g_ms);
    cudaGetSymbolAddress((void**)&pmt, g_mt);
    cudaGetSymbolAddress((void**)&pA0, g_accA0);
    cudaGetSymbolAddress((void**)&pB0, g_accB0);
    cudaGetSymbolAddress((void**)&pA1, g_accA1);
    cudaGetSymbolAddress((void**)&pB1, g_accB1);
    cudaGetSymbolAddress((void**)&pdeg0, g_deg0);
    cudaGetSymbolAddress((void**)&poff0, g_off0);
    cudaGetSymbolAddress((void**)&pcur0, g_cur0);
    cudaGetSymbolAddress((void**)&pdeg1, g_deg1);
    cudaGetSymbolAddress((void**)&poff1, g_off1);
    cudaGetSymbolAddress((void**)&pcur1, g_cur1);
    cudaGetSymbolAddress((void**)&pbs0, g_bsum0);
    cudaGetSymbolAddress((void**)&pbs1, g_bsum1);
    cudaGetSymbolAddress((void**)&pcsr0, g_csr0);
    cudaGetSymbolAddress((void**)&pcsr1, g_csr1);

    const int nb1 = (CN1 + 1023) / 1024;   // 147
    const int nb0 = (CN0 + 1023) / 1024;   // 49

    if (g_init_state == 1) {
        // ---- fork ----
        cudaEventRecord(eRoot, 0);
        cudaStreamWaitEvent(s1, eRoot, 0);
        cudaStreamWaitEvent(s2, eRoot, 0);
        cudaStreamWaitEvent(s3, eRoot, 0);

        // s2: CSR build for E1 (critical: feeds csr_accum1 on main)
        cudaMemsetAsync(pdeg1, 0, sizeof(int) * CN1, s2);
        hist_kernel<<<(CE1 + 255) / 256, 256, 0, s2>>>(adj1 + CE1, pdeg1, CE1);
        scan_block<<<nb1, 1024, 0, s2>>>(pdeg1, poff1, pbs1, CN1);
        scan_top<<<1, 256, 0, s2>>>(pbs1, nb1);
        scan_add<<<(CN1 + 255) / 256, 256, 0, s2>>>(poff1, pbs1, pcur1, CN1);
        reorder_adj<<<(CE1 + 255) / 256, 256, 0, s2>>>(adj1, adj1 + CE1, adj1v, cci1,
                                                       ahbs1, pcur1, pcsr1, CE1);
        cudaEventRecord(eB1, s2);

        // s1: chain0 entirely in-stream — build0, gemm0, csr_accum0, fused0
        cudaMemsetAsync(pdeg0, 0, sizeof(int) * CN0, s1);
        hist_kernel<<<(CE0 + 255) / 256, 256, 0, s1>>>(adj0 + CE0, pdeg0, CE0);
        scan_block<<<nb0, 1024, 0, s1>>>(pdeg0, poff0, pbs0, CN0);
        scan_top<<<1, 256, 0, s1>>>(pbs0, nb0);
        scan_add<<<(CN0 + 255) / 256, 256, 0, s1>>>(poff0, pbs0, pcur0, CN0);
        reorder_adj<<<(CE0 + 255) / 256, 256, 0, s1>>>(adj0, adj0 + CE0, adj0v, cci0,
                                                       ahbs0, pcur0, pcsr0, CE0);
        gemm64_dual<<<(CN0 + 127) / 128, 256, 0, s1>>>(x0, Whbs0, Wt, pm0, pmt, CN0);
        cudaEventRecord(eG0, s1);
        csr_accum<<<(CN0 + 31) / 32, 256, 0, s1>>>(poff0, pdeg0, pcsr0, pm0, pA0, CN0);

        // main: chain1 — gemm(x1)
        gemm64_dual<<<(CN1 + 127) / 128, 256, 0, 0>>>(x1, Whbs1, Ws, pm1, pms, CN1);
        cudaEventRecord(eG1, 0);

        // s3: memset B accumulators + pass-through copies, then incidence scatter
        cudaMemsetAsync(pB0, 0, sizeof(float) * (size_t)CN0 * DD, s3);
        cudaMemsetAsync(pB1, 0, sizeof(float) * (size_t)CN1 * DD, s3);
        cudaMemcpyAsync(out + (long)(CN0 + CN1) * DD, x2, sizeof(float) * (size_t)CN2 * DD,
                        cudaMemcpyDeviceToDevice, s3);
        cudaMemcpyAsync(out + (long)(CN0 + CN1 + CN2) * DD, x3, sizeof(float) * (size_t)CN3 * DD,
                        cudaMemcpyDeviceToDevice, s3);
        cudaMemcpyAsync(out + (long)(CN0 + CN1 + CN2 + CN3) * DD, x4,
                        sizeof(float) * (size_t)CN4 * DD, cudaMemcpyDeviceToDevice, s3);
        cudaStreamWaitEvent(s3, eG0, 0);
        cudaStreamWaitEvent(s3, eG1, 0);
        scatter_inc2<<<CNNZ / 32, 256, 0, s3>>>(pms, pmt, inc, inc + CNNZ, incv,
                                                pB0, pB1, CNNZ);
        cudaEventRecord(eI, s3);

        // s1: fused0 after incidence scatter
        cudaStreamWaitEvent(s1, eI, 0);
        gemm64_fused<<<(CN0 + 127) / 128, 256, 0, s1>>>(pA0, pB0, Wag0, out, CN0);
        cudaEventRecord(eF0, s1);

        // main: csr_accum1 then fused1, join
        cudaStreamWaitEvent(0, eB1, 0);
        csr_accum<<<(CN1 + 31) / 32, 256, 0, 0>>>(poff1, pdeg1, pcsr1, pm1, pA1, CN1);
        cudaStreamWaitEvent(0, eI, 0);
        gemm64_fused<<<(CN1 + 127) / 128, 256, 0, 0>>>(pA1, pB1, Wag1,
                                                       out + (long)CN0 * DD, CN1);
        cudaStreamWaitEvent(0, eF0, 0);  // joins s1 (s2 via eB1, s3 via eI)
    } else {
        // ======== serial fallback ========
        cudaMemsetAsync(pB0, 0, sizeof(float) * (size_t)CN0 * DD);
        cudaMemsetAsync(pB1, 0, sizeof(float) * (size_t)CN1 * DD);
        cudaMemsetAsync(pdeg1, 0, sizeof(int) * CN1);
        hist_kernel<<<(CE1 + 255) / 256, 256>>>(adj1 + CE1, pdeg1, CE1);
        scan_block<<<nb1, 1024>>>(pdeg1, poff1, pbs1, CN1);
        scan_top<<<1, 256>>>(pbs1, nb1);
        scan_add<<<(CN1 + 255) / 256, 256>>>(poff1, pbs1, pcur1, CN1);
        reorder_adj<<<(CE1 + 255) / 256, 256>>>(adj1, adj1 + CE1, adj1v, cci1,
                                                ahbs1, pcur1, pcsr1, CE1);
        cudaMemsetAsync(pdeg0, 0, sizeof(int) * CN0);
        hist_kernel<<<(CE0 + 255) / 256, 256>>>(adj0 + CE0, pdeg0, CE0);
        scan_block<<<nb0, 1024>>>(pdeg0, poff0, pbs0, CN0);
        scan_top<<<1, 256>>>(pbs0, nb0);
        scan_add<<<(CN0 + 255) / 256, 256>>>(poff0, pbs0, pcur0, CN0);
        reorder_adj<<<(CE0 + 255) / 256, 256>>>(adj0, adj0 + CE0, adj0v, cci0,
                                                ahbs0, pcur0, pcsr0, CE0);
        gemm64_dual<<<(CN0 + 127) / 128, 256>>>(x0, Whbs0, Wt, pm0, pmt, CN0);
        gemm64_dual<<<(CN1 + 127) / 128, 256>>>(x1, Whbs1, Ws, pm1, pms, CN1);
        csr_accum<<<(CN0 + 31) / 32, 256>>>(poff0, pdeg0, pcsr0, pm0, pA0, CN0);
        csr_accum<<<(CN1 + 31) / 32, 256>>>(poff1, pdeg1, pcsr1, pm1, pA1, CN1);
        scatter_inc2<<<CNNZ / 32, 256>>>(pms, pmt, inc, inc + CNNZ, incv, pB0, pB1, CNNZ);
        gemm64_fused<<<(CN0 + 127) / 128, 256>>>(pA0, pB0, Wag0, out, CN0);
        gemm64_fused<<<(CN1 + 127) / 128, 256>>>(pA1, pB1, Wag1, out + (long)CN0 * DD, CN1);
        cudaMemcpyAsync(out + (long)(CN0 + CN1) * DD, x2, sizeof(float) * (size_t)CN2 * DD,
                        cudaMemcpyDeviceToDevice);
        cudaMemcpyAsync(out + (long)(CN0 + CN1 + CN2) * DD, x3, sizeof(float) * (size_t)CN3 * DD,
                        cudaMemcpyDeviceToDevice);
        cudaMemcpyAsync(out + (long)(CN0 + CN1 + CN2 + CN3) * DD, x4,
                        sizeof(float) * (size_t)CN4 * DD, cudaMemcpyDeviceToDevice);
    }
}